// round 1
// baseline (speedup 1.0000x reference)
#include <cuda_runtime.h>
#include <cstdint>

#define BN 32
#define BM 64
#define DD 128
#define PAD 132          // smem row stride in floats (bank-conflict-free patterns)
#define THREADS 256
#define MAXM 16384

__device__ float g_y2[MAXM];

__global__ __launch_bounds__(256) void y2_kernel(const float* __restrict__ y, int M) {
    int gw   = (blockIdx.x * blockDim.x + threadIdx.x) >> 5;   // one warp per row
    int lane = threadIdx.x & 31;
    if (gw >= M) return;
    float4 v = ((const float4*)(y + (size_t)gw * DD))[lane];
    float s = v.x * v.x + v.y * v.y + v.z * v.z + v.w * v.w;
#pragma unroll
    for (int o = 16; o; o >>= 1) s += __shfl_xor_sync(0xffffffffu, s, o);
    if (lane == 0) g_y2[gw] = s;
}

__device__ __forceinline__ void cpa16(float* dst, const float* src) {
    uint32_t s = (uint32_t)__cvta_generic_to_shared(dst);
    asm volatile("cp.async.cg.shared.global [%0], [%1], 16;" :: "r"(s), "l"(src));
}

__global__ __launch_bounds__(THREADS, 1) void gmm_kernel(
    const float* __restrict__ x, const float* __restrict__ t,
    const float* __restrict__ y, float* __restrict__ out, int M)
{
    extern __shared__ float sm[];
    float* x_s = sm;                       // BN*PAD
    float* y_n = x_s + BN * PAD;           // 2 * BM * PAD (double buffer)
    float* w_s = y_n + 2 * BM * PAD;       // BN*BM softmax weights
    float* y2s = w_s + BN * BM;            // 2 * BM
    float* sA  = y2s + 2 * BM;             // BN
    float* sC  = sA + BN;                  // BN
    float* sIV = sC + BN;                  // BN

    const int tid  = threadIdx.x;
    const int lane = tid & 31;
    const int w    = tid >> 5;
    const int n0   = blockIdx.x * BN;
    const int r0   = w * 4;                // this warp's 4 rows

    // Per-row VP-SDE stats.  logit = A*dot + C*y2 (+const per row, dropped)
    if (tid < BN) {
        float tt = t[n0 + tid];
        float lm = -0.25f * tt * tt * (20.0f - 0.1f) - 0.5f * tt * 0.1f;
        float mean = expf(lm);
        float var  = fmaxf(1.0f - expf(2.0f * lm), 1e-12f);
        float iv   = 1.0f / var;
        sA[tid]  = iv * mean;
        sC[tid]  = -0.5f * iv * mean * mean;
        sIV[tid] = iv;
    }
    // Stage x block (row-major, padded)
#pragma unroll
    for (int i = tid; i < BN * DD / 4; i += THREADS) {
        int r = i >> 5;
        int c = i & 31;
        float4 v = ((const float4*)(x + (size_t)(n0 + r) * DD))[c];
        *(float4*)&x_s[r * PAD + 4 * c] = v;
    }
    __syncthreads();

    float A[4], C[4], IV[4];
#pragma unroll
    for (int i = 0; i < 4; i++) { A[i] = sA[r0 + i]; C[i] = sC[r0 + i]; IV[i] = sIV[r0 + i]; }

    float ev[4][4];
#pragma unroll
    for (int i = 0; i < 4; i++)
#pragma unroll
        for (int q = 0; q < 4; q++) ev[i][q] = 0.0f;
    float mrow[4], srow[4];
    const float NEG_INF = __int_as_float(0xff800000);
#pragma unroll
    for (int i = 0; i < 4; i++) { mrow[i] = NEG_INF; srow[i] = 0.0f; }

    auto load_tile = [&](int b, int tile) {
        float* buf = y_n + b * (BM * PAD);
        const float* src = y + (size_t)tile * BM * DD;
#pragma unroll
        for (int i = tid; i < BM * DD / 4; i += THREADS) {
            int j = i >> 5;
            int c = i & 31;
            cpa16(&buf[j * PAD + 4 * c], src + j * DD + 4 * c);
        }
        if (tid < BM / 4) cpa16(&y2s[b * BM + 4 * tid], &g_y2[tile * BM + 4 * tid]);
        asm volatile("cp.async.commit_group;");
    };

    const int nt = M / BM;
    load_tile(0, 0);
    int b = 0;
    for (int it = 0; it < nt; ++it) {
        if (it + 1 < nt) {
            load_tile(b ^ 1, it + 1);
            asm volatile("cp.async.wait_group 1;");
        } else {
            asm volatile("cp.async.wait_group 0;");
        }
        __syncthreads();

        float* buf = y_n + b * (BM * PAD);

        // ---- GEMM1: 4 rows x 2 cols per thread, k vectorized by 4 ----
        float acc0[4] = {0.f, 0.f, 0.f, 0.f};
        float acc1[4] = {0.f, 0.f, 0.f, 0.f};
        const float* ya = buf + lane * PAD;          // col j = lane
        const float* yb = buf + (lane + 32) * PAD;   // col j = lane+32
#pragma unroll
        for (int k = 0; k < DD; k += 4) {
            float4 v0 = *(const float4*)(ya + k);
            float4 v1 = *(const float4*)(yb + k);
#pragma unroll
            for (int i = 0; i < 4; i++) {
                float4 xv = *(const float4*)&x_s[(r0 + i) * PAD + k];
                acc0[i] = fmaf(xv.x, v0.x, acc0[i]);
                acc0[i] = fmaf(xv.y, v0.y, acc0[i]);
                acc0[i] = fmaf(xv.z, v0.z, acc0[i]);
                acc0[i] = fmaf(xv.w, v0.w, acc0[i]);
                acc1[i] = fmaf(xv.x, v1.x, acc1[i]);
                acc1[i] = fmaf(xv.y, v1.y, acc1[i]);
                acc1[i] = fmaf(xv.z, v1.z, acc1[i]);
                acc1[i] = fmaf(xv.w, v1.w, acc1[i]);
            }
        }

        // ---- per-warp online softmax (warp owns its 4 rows end-to-end) ----
        float y2a = y2s[b * BM + lane];
        float y2b = y2s[b * BM + lane + 32];
#pragma unroll
        for (int i = 0; i < 4; i++) {
            float l0 = fmaf(A[i], acc0[i], C[i] * y2a);
            float l1 = fmaf(A[i], acc1[i], C[i] * y2b);
            float mx = fmaxf(l0, l1);
#pragma unroll
            for (int o = 16; o; o >>= 1) mx = fmaxf(mx, __shfl_xor_sync(0xffffffffu, mx, o));
            float mn = fmaxf(mrow[i], mx);
            float scale = __expf(mrow[i] - mn);
            mrow[i] = mn;
            float p0 = __expf(l0 - mn);
            float p1 = __expf(l1 - mn);
            float ps = p0 + p1;
#pragma unroll
            for (int o = 16; o; o >>= 1) ps += __shfl_xor_sync(0xffffffffu, ps, o);
            srow[i] = fmaf(srow[i], scale, ps);
#pragma unroll
            for (int q = 0; q < 4; q++) ev[i][q] *= scale;
            w_s[(r0 + i) * BM + lane]      = p0;
            w_s[(r0 + i) * BM + lane + 32] = p1;
        }
        __syncwarp();

        // ---- GEMM2: evals[4 rows][4 d] += w @ y_tile ----
#pragma unroll 4
        for (int j = 0; j < BM; j += 4) {
            float4 yv0 = *(const float4*)&buf[(j + 0) * PAD + 4 * lane];
            float4 yv1 = *(const float4*)&buf[(j + 1) * PAD + 4 * lane];
            float4 yv2 = *(const float4*)&buf[(j + 2) * PAD + 4 * lane];
            float4 yv3 = *(const float4*)&buf[(j + 3) * PAD + 4 * lane];
#pragma unroll
            for (int i = 0; i < 4; i++) {
                float4 wv = *(const float4*)&w_s[(r0 + i) * BM + j];
                ev[i][0] = fmaf(wv.x, yv0.x, ev[i][0]);
                ev[i][1] = fmaf(wv.x, yv0.y, ev[i][1]);
                ev[i][2] = fmaf(wv.x, yv0.z, ev[i][2]);
                ev[i][3] = fmaf(wv.x, yv0.w, ev[i][3]);
                ev[i][0] = fmaf(wv.y, yv1.x, ev[i][0]);
                ev[i][1] = fmaf(wv.y, yv1.y, ev[i][1]);
                ev[i][2] = fmaf(wv.y, yv1.z, ev[i][2]);
                ev[i][3] = fmaf(wv.y, yv1.w, ev[i][3]);
                ev[i][0] = fmaf(wv.z, yv2.x, ev[i][0]);
                ev[i][1] = fmaf(wv.z, yv2.y, ev[i][1]);
                ev[i][2] = fmaf(wv.z, yv2.z, ev[i][2]);
                ev[i][3] = fmaf(wv.z, yv2.w, ev[i][3]);
                ev[i][0] = fmaf(wv.w, yv3.x, ev[i][0]);
                ev[i][1] = fmaf(wv.w, yv3.y, ev[i][1]);
                ev[i][2] = fmaf(wv.w, yv3.z, ev[i][2]);
                ev[i][3] = fmaf(wv.w, yv3.w, ev[i][3]);
            }
        }
        __syncthreads();   // buffer b is free for the load issued next iteration
        b ^= 1;
    }

    // ---- epilogue: out = (evals/sum - x) * inv_var ----
#pragma unroll
    for (int i = 0; i < 4; i++) {
        float invs = 1.0f / srow[i];
        float4 xv = *(const float4*)&x_s[(r0 + i) * PAD + 4 * lane];
        float4 o;
        o.x = (ev[i][0] * invs - xv.x) * IV[i];
        o.y = (ev[i][1] * invs - xv.y) * IV[i];
        o.z = (ev[i][2] * invs - xv.z) * IV[i];
        o.w = (ev[i][3] * invs - xv.w) * IV[i];
        *(float4*)(out + (size_t)(n0 + r0 + i) * DD + 4 * lane) = o;
    }
}

extern "C" void kernel_launch(void* const* d_in, const int* in_sizes, int n_in,
                              void* d_out, int out_size) {
    const float* x = (const float*)d_in[0];
    const float* t = (const float*)d_in[1];
    const float* y = (const float*)d_in[2];
    float* out = (float*)d_out;
    const int N = in_sizes[1];          // t has N elements
    const int M = in_sizes[2] / DD;

    size_t smem = (size_t)(BN * PAD + 2 * BM * PAD + BN * BM + 2 * BM + 3 * BN) * sizeof(float);
    cudaFuncSetAttribute(gmm_kernel, cudaFuncAttributeMaxDynamicSharedMemorySize, (int)smem);

    y2_kernel<<<(M + 7) / 8, 256>>>(y, M);
    gmm_kernel<<<N / BN, THREADS, smem>>>(x, t, y, out, M);
}

// round 2
// speedup vs baseline: 1.0017x; 1.0017x over previous
#include <cuda_runtime.h>
#include <cstdint>

#define BN 32
#define BM 64
#define DD 128
#define PAD 132          // smem row stride in floats (bank-conflict-free patterns)
#define THREADS 256
#define MAXM 16384

__device__ float g_y2[MAXM];

__global__ __launch_bounds__(256) void y2_kernel(const float* __restrict__ y, int M) {
    int gw   = (blockIdx.x * blockDim.x + threadIdx.x) >> 5;   // one warp per row
    int lane = threadIdx.x & 31;
    if (gw >= M) return;
    float4 v = ((const float4*)(y + (size_t)gw * DD))[lane];
    float s = v.x * v.x + v.y * v.y + v.z * v.z + v.w * v.w;
#pragma unroll
    for (int o = 16; o; o >>= 1) s += __shfl_xor_sync(0xffffffffu, s, o);
    if (lane == 0) g_y2[gw] = s;
}

__device__ __forceinline__ void cpa16(float* dst, const float* src) {
    uint32_t s = (uint32_t)__cvta_generic_to_shared(dst);
    asm volatile("cp.async.cg.shared.global [%0], [%1], 16;" :: "r"(s), "l"(src));
}

__global__ __launch_bounds__(THREADS, 1) void gmm_kernel(
    const float* __restrict__ x, const float* __restrict__ t,
    const float* __restrict__ y, float* __restrict__ out, int M)
{
    extern __shared__ float sm[];
    float* x_s = sm;                       // BN*PAD
    float* y_n = x_s + BN * PAD;           // 2 * BM * PAD (double buffer)
    float* w_s = y_n + 2 * BM * PAD;       // BN*BM softmax weights
    float* y2s = w_s + BN * BM;            // 2 * BM
    float* sA  = y2s + 2 * BM;             // BN
    float* sC  = sA + BN;                  // BN
    float* sIV = sC + BN;                  // BN

    const int tid  = threadIdx.x;
    const int lane = tid & 31;
    const int w    = tid >> 5;
    const int n0   = blockIdx.x * BN;
    const int r0   = w * 4;                // this warp's 4 rows

    // Per-row VP-SDE stats.  logit = A*dot + C*y2 (+const per row, dropped)
    if (tid < BN) {
        float tt = t[n0 + tid];
        float lm = -0.25f * tt * tt * (20.0f - 0.1f) - 0.5f * tt * 0.1f;
        float mean = expf(lm);
        float var  = fmaxf(1.0f - expf(2.0f * lm), 1e-12f);
        float iv   = 1.0f / var;
        sA[tid]  = iv * mean;
        sC[tid]  = -0.5f * iv * mean * mean;
        sIV[tid] = iv;
    }
    // Stage x block (row-major, padded)
#pragma unroll
    for (int i = tid; i < BN * DD / 4; i += THREADS) {
        int r = i >> 5;
        int c = i & 31;
        float4 v = ((const float4*)(x + (size_t)(n0 + r) * DD))[c];
        *(float4*)&x_s[r * PAD + 4 * c] = v;
    }
    __syncthreads();

    float A[4], C[4], IV[4];
#pragma unroll
    for (int i = 0; i < 4; i++) { A[i] = sA[r0 + i]; C[i] = sC[r0 + i]; IV[i] = sIV[r0 + i]; }

    float ev[4][4];
#pragma unroll
    for (int i = 0; i < 4; i++)
#pragma unroll
        for (int q = 0; q < 4; q++) ev[i][q] = 0.0f;
    float mrow[4], srow[4];
    const float NEG_INF = __int_as_float(0xff800000);
#pragma unroll
    for (int i = 0; i < 4; i++) { mrow[i] = NEG_INF; srow[i] = 0.0f; }

    auto load_tile = [&](int b, int tile) {
        float* buf = y_n + b * (BM * PAD);
        const float* src = y + (size_t)tile * BM * DD;
#pragma unroll
        for (int i = tid; i < BM * DD / 4; i += THREADS) {
            int j = i >> 5;
            int c = i & 31;
            cpa16(&buf[j * PAD + 4 * c], src + j * DD + 4 * c);
        }
        if (tid < BM / 4) cpa16(&y2s[b * BM + 4 * tid], &g_y2[tile * BM + 4 * tid]);
        asm volatile("cp.async.commit_group;");
    };

    const int nt = M / BM;
    load_tile(0, 0);
    int b = 0;
    for (int it = 0; it < nt; ++it) {
        if (it + 1 < nt) {
            load_tile(b ^ 1, it + 1);
            asm volatile("cp.async.wait_group 1;");
        } else {
            asm volatile("cp.async.wait_group 0;");
        }
        __syncthreads();

        float* buf = y_n + b * (BM * PAD);

        // ---- GEMM1: 4 rows x 2 cols per thread, k vectorized by 4 ----
        float acc0[4] = {0.f, 0.f, 0.f, 0.f};
        float acc1[4] = {0.f, 0.f, 0.f, 0.f};
        const float* ya = buf + lane * PAD;          // col j = lane
        const float* yb = buf + (lane + 32) * PAD;   // col j = lane+32
#pragma unroll
        for (int k = 0; k < DD; k += 4) {
            float4 v0 = *(const float4*)(ya + k);
            float4 v1 = *(const float4*)(yb + k);
#pragma unroll
            for (int i = 0; i < 4; i++) {
                float4 xv = *(const float4*)&x_s[(r0 + i) * PAD + k];
                acc0[i] = fmaf(xv.x, v0.x, acc0[i]);
                acc0[i] = fmaf(xv.y, v0.y, acc0[i]);
                acc0[i] = fmaf(xv.z, v0.z, acc0[i]);
                acc0[i] = fmaf(xv.w, v0.w, acc0[i]);
                acc1[i] = fmaf(xv.x, v1.x, acc1[i]);
                acc1[i] = fmaf(xv.y, v1.y, acc1[i]);
                acc1[i] = fmaf(xv.z, v1.z, acc1[i]);
                acc1[i] = fmaf(xv.w, v1.w, acc1[i]);
            }
        }

        // ---- per-warp online softmax (warp owns its 4 rows end-to-end) ----
        float y2a = y2s[b * BM + lane];
        float y2b = y2s[b * BM + lane + 32];
#pragma unroll
        for (int i = 0; i < 4; i++) {
            float l0 = fmaf(A[i], acc0[i], C[i] * y2a);
            float l1 = fmaf(A[i], acc1[i], C[i] * y2b);
            float mx = fmaxf(l0, l1);
#pragma unroll
            for (int o = 16; o; o >>= 1) mx = fmaxf(mx, __shfl_xor_sync(0xffffffffu, mx, o));
            float mn = fmaxf(mrow[i], mx);
            float scale = __expf(mrow[i] - mn);
            mrow[i] = mn;
            float p0 = __expf(l0 - mn);
            float p1 = __expf(l1 - mn);
            float ps = p0 + p1;
#pragma unroll
            for (int o = 16; o; o >>= 1) ps += __shfl_xor_sync(0xffffffffu, ps, o);
            srow[i] = fmaf(srow[i], scale, ps);
#pragma unroll
            for (int q = 0; q < 4; q++) ev[i][q] *= scale;
            w_s[(r0 + i) * BM + lane]      = p0;
            w_s[(r0 + i) * BM + lane + 32] = p1;
        }
        __syncwarp();

        // ---- GEMM2: evals[4 rows][4 d] += w @ y_tile ----
#pragma unroll 4
        for (int j = 0; j < BM; j += 4) {
            float4 yv0 = *(const float4*)&buf[(j + 0) * PAD + 4 * lane];
            float4 yv1 = *(const float4*)&buf[(j + 1) * PAD + 4 * lane];
            float4 yv2 = *(const float4*)&buf[(j + 2) * PAD + 4 * lane];
            float4 yv3 = *(const float4*)&buf[(j + 3) * PAD + 4 * lane];
#pragma unroll
            for (int i = 0; i < 4; i++) {
                float4 wv = *(const float4*)&w_s[(r0 + i) * BM + j];
                ev[i][0] = fmaf(wv.x, yv0.x, ev[i][0]);
                ev[i][1] = fmaf(wv.x, yv0.y, ev[i][1]);
                ev[i][2] = fmaf(wv.x, yv0.z, ev[i][2]);
                ev[i][3] = fmaf(wv.x, yv0.w, ev[i][3]);
                ev[i][0] = fmaf(wv.y, yv1.x, ev[i][0]);
                ev[i][1] = fmaf(wv.y, yv1.y, ev[i][1]);
                ev[i][2] = fmaf(wv.y, yv1.z, ev[i][2]);
                ev[i][3] = fmaf(wv.y, yv1.w, ev[i][3]);
                ev[i][0] = fmaf(wv.z, yv2.x, ev[i][0]);
                ev[i][1] = fmaf(wv.z, yv2.y, ev[i][1]);
                ev[i][2] = fmaf(wv.z, yv2.z, ev[i][2]);
                ev[i][3] = fmaf(wv.z, yv2.w, ev[i][3]);
                ev[i][0] = fmaf(wv.w, yv3.x, ev[i][0]);
                ev[i][1] = fmaf(wv.w, yv3.y, ev[i][1]);
                ev[i][2] = fmaf(wv.w, yv3.z, ev[i][2]);
                ev[i][3] = fmaf(wv.w, yv3.w, ev[i][3]);
            }
        }
        __syncthreads();   // buffer b is free for the load issued next iteration
        b ^= 1;
    }

    // ---- epilogue: out = (evals/sum - x) * inv_var ----
#pragma unroll
    for (int i = 0; i < 4; i++) {
        float invs = 1.0f / srow[i];
        float4 xv = *(const float4*)&x_s[(r0 + i) * PAD + 4 * lane];
        float4 o;
        o.x = (ev[i][0] * invs - xv.x) * IV[i];
        o.y = (ev[i][1] * invs - xv.y) * IV[i];
        o.z = (ev[i][2] * invs - xv.z) * IV[i];
        o.w = (ev[i][3] * invs - xv.w) * IV[i];
        *(float4*)(out + (size_t)(n0 + r0 + i) * DD + 4 * lane) = o;
    }
}

extern "C" void kernel_launch(void* const* d_in, const int* in_sizes, int n_in,
                              void* d_out, int out_size) {
    const float* x = (const float*)d_in[0];
    const float* t = (const float*)d_in[1];
    const float* y = (const float*)d_in[2];
    float* out = (float*)d_out;
    const int N = in_sizes[1];          // t has N elements
    const int M = in_sizes[2] / DD;

    size_t smem = (size_t)(BN * PAD + 2 * BM * PAD + BN * BM + 2 * BM + 3 * BN) * sizeof(float);
    cudaFuncSetAttribute(gmm_kernel, cudaFuncAttributeMaxDynamicSharedMemorySize, (int)smem);

    y2_kernel<<<(M + 7) / 8, 256>>>(y, M);
    gmm_kernel<<<N / BN, THREADS, smem>>>(x, t, y, out, M);
}

// round 4
// speedup vs baseline: 1.4214x; 1.4191x over previous
#include <cuda_runtime.h>
#include <cstdint>

#define BN 64
#define BM 128
#define DD 128
#define PAD 132
#define THREADS 256
#define NMAX 4096
#define MMAX 16384

typedef unsigned long long u64;

__device__ float g_y2[MMAX];
__device__ float g_pev[2][NMAX][DD];
__device__ float g_pm[2][NMAX];
__device__ float g_ps[2][NMAX];

#define FMA2(d,a,b) asm("fma.rn.f32x2 %0,%1,%2,%0;" : "+l"(d) : "l"(a), "l"(b))
#define MUL2(d,a,b) asm("mul.rn.f32x2 %0,%1,%2;" : "=l"(d) : "l"(a), "l"(b))
#define UNPACK(lo,hi,p) asm("mov.b64 {%0,%1},%2;" : "=f"(lo), "=f"(hi) : "l"(p))
#define PACK(d,lo,hi) asm("mov.b64 %0,{%1,%2};" : "=l"(d) : "f"(lo), "f"(hi))
#define DUP(d,v) asm("mov.b64 %0,{%1,%1};" : "=l"(d) : "f"(v))

__global__ __launch_bounds__(256) void y2_kernel(const float* __restrict__ y, int M) {
    int gw   = (blockIdx.x * blockDim.x + threadIdx.x) >> 5;
    int lane = threadIdx.x & 31;
    if (gw >= M) return;
    float4 v = ((const float4*)(y + (size_t)gw * DD))[lane];
    float s = v.x * v.x + v.y * v.y + v.z * v.z + v.w * v.w;
#pragma unroll
    for (int o = 16; o; o >>= 1) s += __shfl_xor_sync(0xffffffffu, s, o);
    if (lane == 0) g_y2[gw] = s;
}

__device__ __forceinline__ void cpa16(float* dst, const float* src) {
    uint32_t s = (uint32_t)__cvta_generic_to_shared(dst);
    asm volatile("cp.async.cg.shared.global [%0], [%1], 16;" :: "r"(s), "l"(src));
}

__global__ __launch_bounds__(THREADS, 1) void gmm_kernel(
    const float* __restrict__ x, const float* __restrict__ t,
    const float* __restrict__ y, int M)
{
    extern __shared__ float sm[];
    float* x_s = sm;                       // BN*PAD (A-scaled x)
    float* y_n = x_s + BN * PAD;           // 2 * BM * PAD
    float* w_s = y_n + 2 * BM * PAD;       // 8 warps * BM * 8 (row-interleaved)
    float* y2s = w_s + 8 * BM * 8;         // 2 * BM
    float* sA  = y2s + 2 * BM;             // BN
    float* sC  = sA + BN;                  // BN

    const int tid  = threadIdx.x;
    const int lane = tid & 31;
    const int w    = tid >> 5;
    const int n0   = blockIdx.x * BN;
    const int half = blockIdx.y;
    const int halfM = M >> 1;
    const float* yg  = y + (size_t)half * halfM * DD;
    const float* y2g = g_y2 + (size_t)half * halfM;
    const int r0 = w * 8;
    float* w_w = w_s + w * (BM * 8);

    if (tid < BN) {
        float tt = t[n0 + tid];
        float lm = -0.25f * tt * tt * (20.0f - 0.1f) - 0.5f * tt * 0.1f;
        float mean = expf(lm);
        float var  = fmaxf(1.0f - expf(2.0f * lm), 1e-12f);
        float iv   = 1.0f / var;
        sA[tid] = iv * mean;
        sC[tid] = -0.5f * iv * mean * mean;
    }
    __syncthreads();

    // stage x pre-scaled by A (logit = <A*x, y> + C*y2)
#pragma unroll
    for (int i = tid; i < BN * DD / 4; i += THREADS) {
        int r = i >> 5, c = i & 31;
        float4 v = ((const float4*)(x + (size_t)(n0 + r) * DD))[c];
        float a = sA[r];
        v.x *= a; v.y *= a; v.z *= a; v.w *= a;
        *(float4*)&x_s[r * PAD + 4 * c] = v;
    }

    float C[8];
#pragma unroll
    for (int i = 0; i < 8; i++) C[i] = sC[r0 + i];

    // persistent state: ev pairs over row-pairs: ev[rp][d] = (row 2rp, row 2rp+1)
    u64 ev[4][4];
#pragma unroll
    for (int a = 0; a < 4; a++)
#pragma unroll
        for (int d = 0; d < 4; d++) ev[a][d] = 0ULL;
    float mrow[8], srow[8];
    const float NEG_INF = __int_as_float(0xff800000);
#pragma unroll
    for (int i = 0; i < 8; i++) { mrow[i] = NEG_INF; srow[i] = 0.0f; }

    auto load_tile = [&](int b, int tile) {
        float* buf = y_n + b * (BM * PAD);
        const float* src = yg + (size_t)tile * BM * DD;
#pragma unroll
        for (int i = tid; i < BM * DD / 4; i += THREADS) {
            int j = i >> 5, c = i & 31;
            cpa16(&buf[j * PAD + 4 * c], src + j * DD + 4 * c);
        }
        if (tid < BM / 4) cpa16(&y2s[b * BM + 4 * tid], y2g + tile * BM + 4 * tid);
        asm volatile("cp.async.commit_group;");
    };

    const int nt = halfM / BM;
    load_tile(0, 0);
    int b = 0;
    for (int it = 0; it < nt; ++it) {
        if (it + 1 < nt) {
            load_tile(b ^ 1, it + 1);
            asm volatile("cp.async.wait_group 1;");
        } else {
            asm volatile("cp.async.wait_group 0;");
        }
        __syncthreads();

        float* buf = y_n + b * (BM * PAD);

        // ---- GEMM1: 8 rows x 4 cols per thread, packed f32x2 over k ----
        u64 acc[8][4];
#pragma unroll
        for (int i = 0; i < 8; i++)
#pragma unroll
            for (int c = 0; c < 4; c++) acc[i][c] = 0ULL;

#pragma unroll 2
        for (int k = 0; k < DD; k += 4) {
            ulonglong2 yv0 = *(const ulonglong2*)&buf[(lane      ) * PAD + k];
            ulonglong2 yv1 = *(const ulonglong2*)&buf[(lane +  32) * PAD + k];
            ulonglong2 yv2 = *(const ulonglong2*)&buf[(lane +  64) * PAD + k];
            ulonglong2 yv3 = *(const ulonglong2*)&buf[(lane +  96) * PAD + k];
#pragma unroll
            for (int h = 0; h < 2; h++) {
                ulonglong2 xv[4];
#pragma unroll
                for (int i = 0; i < 4; i++)
                    xv[i] = *(const ulonglong2*)&x_s[(r0 + 4 * h + i) * PAD + k];
#pragma unroll
                for (int i = 0; i < 4; i++) {
                    FMA2(acc[4 * h + i][0], xv[i].x, yv0.x);
                    FMA2(acc[4 * h + i][1], xv[i].x, yv1.x);
                    FMA2(acc[4 * h + i][2], xv[i].x, yv2.x);
                    FMA2(acc[4 * h + i][3], xv[i].x, yv3.x);
                }
#pragma unroll
                for (int i = 0; i < 4; i++) {
                    FMA2(acc[4 * h + i][0], xv[i].y, yv0.y);
                    FMA2(acc[4 * h + i][1], xv[i].y, yv1.y);
                    FMA2(acc[4 * h + i][2], xv[i].y, yv2.y);
                    FMA2(acc[4 * h + i][3], xv[i].y, yv3.y);
                }
            }
        }

        // ---- logits ----
        float lv[8][4];
#pragma unroll
        for (int i = 0; i < 8; i++)
#pragma unroll
            for (int c = 0; c < 4; c++) {
                float lo, hi; UNPACK(lo, hi, acc[i][c]);
                lv[i][c] = lo + hi;
            }
        float y2v[4];
#pragma unroll
        for (int c = 0; c < 4; c++) y2v[c] = y2s[b * BM + lane + 32 * c];
#pragma unroll
        for (int i = 0; i < 8; i++)
#pragma unroll
            for (int c = 0; c < 4; c++) lv[i][c] = fmaf(C[i], y2v[c], lv[i][c]);

        // ---- per-warp online softmax (8 independent row chains) ----
        float mx[8];
#pragma unroll
        for (int i = 0; i < 8; i++)
            mx[i] = fmaxf(fmaxf(lv[i][0], lv[i][1]), fmaxf(lv[i][2], lv[i][3]));
#pragma unroll
        for (int o = 16; o; o >>= 1)
#pragma unroll
            for (int i = 0; i < 8; i++)
                mx[i] = fmaxf(mx[i], __shfl_xor_sync(0xffffffffu, mx[i], o));

        float scl[8], ps[8];
#pragma unroll
        for (int i = 0; i < 8; i++) {
            float mn = fmaxf(mrow[i], mx[i]);
            scl[i] = __expf(mrow[i] - mn);
            mrow[i] = mn;
        }
        float pv[8][4];
#pragma unroll
        for (int i = 0; i < 8; i++) {
#pragma unroll
            for (int c = 0; c < 4; c++) pv[i][c] = __expf(lv[i][c] - mrow[i]);
            ps[i] = (pv[i][0] + pv[i][1]) + (pv[i][2] + pv[i][3]);
        }
#pragma unroll
        for (int o = 16; o; o >>= 1)
#pragma unroll
            for (int i = 0; i < 8; i++)
                ps[i] += __shfl_xor_sync(0xffffffffu, ps[i], o);
#pragma unroll
        for (int i = 0; i < 8; i++) srow[i] = fmaf(srow[i], scl[i], ps[i]);

        // rescale ev accumulators (pairs over rows)
#pragma unroll
        for (int a = 0; a < 4; a++) {
            u64 s2; PACK(s2, scl[2 * a], scl[2 * a + 1]);
#pragma unroll
            for (int d = 0; d < 4; d++) MUL2(ev[a][d], ev[a][d], s2);
        }

        // store weights row-interleaved: w_w[8*j + r] = p[r][j]
#pragma unroll
        for (int c = 0; c < 4; c++) {
            int j = lane + 32 * c;
            *(float4*)&w_w[8 * j]     = make_float4(pv[0][c], pv[1][c], pv[2][c], pv[3][c]);
            *(float4*)&w_w[8 * j + 4] = make_float4(pv[4][c], pv[5][c], pv[6][c], pv[7][c]);
        }
        __syncwarp();

        // ---- GEMM2: ev[row-pair][d] += (w_r0,w_r1) * (y_d,y_d) ----
#pragma unroll 2
        for (int j = 0; j < BM; j++) {
            ulonglong2 wa = *(const ulonglong2*)&w_w[8 * j];       // rows 0-3
            ulonglong2 wb = *(const ulonglong2*)&w_w[8 * j + 4];   // rows 4-7
            ulonglong2 yv = *(const ulonglong2*)&buf[j * PAD + 4 * lane];
            float q0, q1, q2, q3;
            UNPACK(q0, q1, yv.x);
            UNPACK(q2, q3, yv.y);
            u64 d0, d1, d2, d3;
            DUP(d0, q0); DUP(d1, q1); DUP(d2, q2); DUP(d3, q3);
            FMA2(ev[0][0], wa.x, d0); FMA2(ev[0][1], wa.x, d1);
            FMA2(ev[0][2], wa.x, d2); FMA2(ev[0][3], wa.x, d3);
            FMA2(ev[1][0], wa.y, d0); FMA2(ev[1][1], wa.y, d1);
            FMA2(ev[1][2], wa.y, d2); FMA2(ev[1][3], wa.y, d3);
            FMA2(ev[2][0], wb.x, d0); FMA2(ev[2][1], wb.x, d1);
            FMA2(ev[2][2], wb.x, d2); FMA2(ev[2][3], wb.x, d3);
            FMA2(ev[3][0], wb.y, d0); FMA2(ev[3][1], wb.y, d1);
            FMA2(ev[3][2], wb.y, d2); FMA2(ev[3][3], wb.y, d3);
        }
        __syncthreads();
        b ^= 1;
    }

    // ---- write un-normalized partials ----
#pragma unroll
    for (int a = 0; a < 4; a++) {
        float e0[4], e1[4];
#pragma unroll
        for (int d = 0; d < 4; d++) UNPACK(e0[d], e1[d], ev[a][d]);
        *(float4*)&g_pev[half][n0 + r0 + 2 * a    ][4 * lane] = make_float4(e0[0], e0[1], e0[2], e0[3]);
        *(float4*)&g_pev[half][n0 + r0 + 2 * a + 1][4 * lane] = make_float4(e1[0], e1[1], e1[2], e1[3]);
    }
    if (lane == 0) {
#pragma unroll
        for (int i = 0; i < 8; i++) {
            g_pm[half][n0 + r0 + i] = mrow[i];
            g_ps[half][n0 + r0 + i] = srow[i];
        }
    }
}

__global__ __launch_bounds__(256) void combine_kernel(
    const float* __restrict__ x, const float* __restrict__ t,
    float* __restrict__ out, int N)
{
    int row  = blockIdx.x * 8 + (threadIdx.x >> 5);
    int lane = threadIdx.x & 31;
    if (row >= N) return;
    float m0 = g_pm[0][row], m1 = g_pm[1][row];
    float s0 = g_ps[0][row], s1 = g_ps[1][row];
    float mxv = fmaxf(m0, m1);
    float a0 = __expf(m0 - mxv), a1 = __expf(m1 - mxv);
    float inv = 1.0f / fmaf(s0, a0, s1 * a1);
    float tt = t[row];
    float lm = -0.25f * tt * tt * (20.0f - 0.1f) - 0.5f * tt * 0.1f;
    float var = fmaxf(1.0f - expf(2.0f * lm), 1e-12f);
    float iv = 1.0f / var;
    float4 e0 = ((const float4*)g_pev[0][row])[lane];
    float4 e1 = ((const float4*)g_pev[1][row])[lane];
    float4 xv = ((const float4*)(x + (size_t)row * DD))[lane];
    float4 o;
    o.x = (fmaf(e0.x, a0, e1.x * a1) * inv - xv.x) * iv;
    o.y = (fmaf(e0.y, a0, e1.y * a1) * inv - xv.y) * iv;
    o.z = (fmaf(e0.z, a0, e1.z * a1) * inv - xv.z) * iv;
    o.w = (fmaf(e0.w, a0, e1.w * a1) * inv - xv.w) * iv;
    ((float4*)(out + (size_t)row * DD))[lane] = o;
}

extern "C" void kernel_launch(void* const* d_in, const int* in_sizes, int n_in,
                              void* d_out, int out_size) {
    const float* x = (const float*)d_in[0];
    const float* t = (const float*)d_in[1];
    const float* y = (const float*)d_in[2];
    float* out = (float*)d_out;
    const int N = in_sizes[1];
    const int M = in_sizes[2] / DD;

    size_t smem = (size_t)(BN * PAD + 2 * BM * PAD + 8 * BM * 8 + 2 * BM + 2 * BN) * sizeof(float);
    cudaFuncSetAttribute(gmm_kernel, cudaFuncAttributeMaxDynamicSharedMemorySize, (int)smem);

    y2_kernel<<<(M + 7) / 8, 256>>>(y, M);
    gmm_kernel<<<dim3(N / BN, 2), THREADS, smem>>>(x, t, y, M);
    combine_kernel<<<(N + 7) / 8, 256>>>(x, t, out, N);
}